// round 16
// baseline (speedup 1.0000x reference)
#include <cuda_runtime.h>
#include <cuda_fp16.h>
#include <cstdint>

#define N_NODES 200000
#define HID 32

// ---------------- scratch (static device globals; no allocation) ----------
__device__ int   g_deg[N_NODES];
__device__ float g_dinv[N_NODES];
__device__ float g_acc1[N_NODES];
__device__ float g_h2 [N_NODES * HID];   // h2 PRE-SCALED by dinv[n]
__device__ float g_acc2[N_NODES * HID];
__device__ float g_x2 [N_NODES * HID];
__device__ float g_y  [N_NODES * 64];    // per-node layer1 ctx partial (1/3 folded)

// ---------------- GCN stages ------------------------------------------------
__global__ void k_init(const float* __restrict__ ec, float* __restrict__ out_edge, int E) {
    int i = blockIdx.x * blockDim.x + threadIdx.x;
    if (i < N_NODES * HID / 4) ((float4*)g_acc2)[i] = make_float4(0.f, 0.f, 0.f, 0.f);
    if (i < N_NODES) { g_deg[i] = 0; g_acc1[i] = 0.f; }
    if (i < E) out_edge[i] = ec[i];
}
__global__ void k_deg(const int* __restrict__ dst, int E) {
    int e = blockIdx.x * blockDim.x + threadIdx.x;
    if (e < E) atomicAdd(&g_deg[dst[e]], 1);
}
__global__ void k_dinv() {
    int n = blockIdx.x * blockDim.x + threadIdx.x;
    if (n < N_NODES) g_dinv[n] = rsqrtf((float)(g_deg[n] + 1));
}
__global__ void k_acc1(const int* __restrict__ src, const int* __restrict__ dst, int E) {
    int e = blockIdx.x * blockDim.x + threadIdx.x;
    if (e < E) atomicAdd(&g_acc1[dst[e]], g_dinv[src[e]]);
}
__global__ void k_node1(const float* __restrict__ W1, const float* __restrict__ b1,
                        const float* __restrict__ W2) {
    __shared__ float sW1[HID], sB1[HID], sW2[HID * HID];
    for (int i = threadIdx.x; i < HID; i += blockDim.x) { sW1[i] = W1[i]; sB1[i] = b1[i]; }
    for (int i = threadIdx.x; i < HID * HID; i += blockDim.x) sW2[i] = W2[i];
    __syncthreads();
    int n = blockIdx.x * blockDim.x + threadIdx.x;
    if (n >= N_NODES) return;
    float dv = g_dinv[n];
    float s1 = dv * (g_acc1[n] + dv);
    float x1[HID];
#pragma unroll
    for (int k = 0; k < HID; k++) x1[k] = fmaxf(fmaf(sW1[k], s1, sB1[k]), 0.f);
    float h2[HID];
#pragma unroll
    for (int j = 0; j < HID; j++) h2[j] = 0.f;
#pragma unroll
    for (int i = 0; i < HID; i++) {
        float xi = x1[i];
#pragma unroll
        for (int j = 0; j < HID; j++) h2[j] = fmaf(xi, sW2[i * HID + j], h2[j]);
    }
    float4* o = (float4*)(g_h2 + (size_t)n * HID);
#pragma unroll
    for (int q = 0; q < 8; q++)
        o[q] = make_float4(h2[4 * q] * dv, h2[4 * q + 1] * dv,
                           h2[4 * q + 2] * dv, h2[4 * q + 3] * dv);
}
__global__ void k_msg(const int* __restrict__ src, const int* __restrict__ dst, int E) {
    int idx = blockIdx.x * blockDim.x + threadIdx.x;
    int e = idx >> 3, k = (idx & 7) << 2;
    if (e >= E) return;
    int s = src[e], d = dst[e];
    float nrm = g_dinv[d];
    float4 v = *(const float4*)(g_h2 + (size_t)s * HID + k);
    float* p = g_acc2 + (size_t)d * HID + k;
    asm volatile("red.global.add.v4.f32 [%0], {%1,%2,%3,%4};"
                 :: "l"(p), "f"(v.x * nrm), "f"(v.y * nrm), "f"(v.z * nrm), "f"(v.w * nrm)
                 : "memory");
}
__global__ void k_node2(const float* __restrict__ b2) {
    int i = blockIdx.x * blockDim.x + threadIdx.x;
    if (i >= N_NODES * HID) return;
    int n = i >> 5, k = i & 31;
    float dv = g_dinv[n];
    g_x2[i] = fmaxf(g_acc2[i] + g_h2[i] * dv + b2[k], 0.f);
}
// per-node layer1 ctx partial: y[n] = (1/3) * W1[3:35,:]^T x2[n]
__global__ void k_y(const float* __restrict__ Wm1) {
    __shared__ float sW[32 * 64];
    for (int i = threadIdx.x; i < 32 * 64; i += blockDim.x)
        sW[i] = Wm1[(3 + (i >> 6)) * 64 + (i & 63)] * (1.f / 3.f);
    __syncthreads();
    int idx = blockIdx.x * blockDim.x + threadIdx.x;
    int n = idx >> 3, oct = idx & 7;
    if (n >= N_NODES) return;
    const float* x = g_x2 + (size_t)n * HID;
    float acc[8] = {0.f, 0.f, 0.f, 0.f, 0.f, 0.f, 0.f, 0.f};
#pragma unroll 8
    for (int i = 0; i < 32; i++) {
        float xi = __ldg(x + i);
        const float* w = sW + i * 64 + oct * 8;
#pragma unroll
        for (int o = 0; o < 8; o++) acc[o] = fmaf(xi, w[o], acc[o]);
    }
    float4* yo = (float4*)(g_y + (size_t)n * 64 + oct * 8);
    yo[0] = make_float4(acc[0], acc[1], acc[2], acc[3]);
    yo[1] = make_float4(acc[4], acc[5], acc[6], acc[7]);
}

// ---------------- stage 7: triangle MLP, 26 MMAs/tile ------------------------
#define WPB  4
#define TILE 16
#define SYS  68     // ysum stride (floats)
#define SAH  56     // h2 staging stride (halves)
#define SHH  72     // h1 staging stride (halves)
// per-warp regions (bytes)
#define WB_AS 0                       // small-A [16][8] half = 256
#define WB_Y  256                     // ysum [16][68] f32 = 4352 (reused as h2 half staging)
#define WB_H  4608                    // h1 [16][72] half = 2304 (sIdx + sD live here too)
#define WARP_BYTES 6912
// block layout
#define OFF_W1S 0                     // 8*32 uint32 = 1024
#define OFF_B1B 1024
#define OFF_B2B 1280
#define OFF_B3B 1408
#define OFF_STG 1424
#define SMEM_BYTES (OFF_STG + WPB * WARP_BYTES)   // 29072

__device__ __forceinline__ uint32_t packh2(float lo, float hi) {
    __half2 h = __floats2half2_rn(lo, hi);
    return *(uint32_t*)&h;
}
__device__ __forceinline__ void mma_f16(
    float& c0, float& c1, float& c2, float& c3,
    uint32_t a0, uint32_t a1, uint32_t a2, uint32_t a3,
    uint32_t b0, uint32_t b1)
{
    asm volatile(
        "mma.sync.aligned.m16n8k16.row.col.f32.f16.f16.f32 "
        "{%0,%1,%2,%3},{%4,%5,%6,%7},{%8,%9},{%0,%1,%2,%3};"
        : "+f"(c0), "+f"(c1), "+f"(c2), "+f"(c3)
        : "r"(a0), "r"(a1), "r"(a2), "r"(a3), "r"(b0), "r"(b1));
}
__device__ __forceinline__ void mma_f16_k8(
    float& c0, float& c1, float& c2, float& c3,
    uint32_t a0, uint32_t a1, uint32_t b0)
{
    asm volatile(
        "mma.sync.aligned.m16n8k8.row.col.f32.f16.f16.f32 "
        "{%0,%1,%2,%3},{%4,%5},{%6},{%0,%1,%2,%3};"
        : "+f"(c0), "+f"(c1), "+f"(c2), "+f"(c3)
        : "r"(a0), "r"(a1), "r"(b0));
}

__global__ void __launch_bounds__(WPB * 32, 4) k_tri(
    const float* __restrict__ t12, const float* __restrict__ t13, const float* __restrict__ t23,
    const int* __restrict__ c12, const int* __restrict__ c13, const int* __restrict__ c23,
    const float* __restrict__ ec,
    const float* __restrict__ Wm1, const float* __restrict__ bm1,
    const float* __restrict__ Wm2, const float* __restrict__ bm2,
    const float* __restrict__ Wm3, const float* __restrict__ bm3,
    float* __restrict__ out_edge,
    float* __restrict__ o12, float* __restrict__ o13, float* __restrict__ o23, int T)
{
    extern __shared__ char smem[];
    uint32_t* sW1s = (uint32_t*)(smem + OFF_W1S);   // [nt*32 + qd*8+grp]
    float* sB1 = (float*)(smem + OFF_B1B);
    float* sB2 = (float*)(smem + OFF_B2B);
    float* sB3 = (float*)(smem + OFF_B3B);
    char*  stage = smem + OFF_STG;

    const int tid = threadIdx.x;

    // ---- W1small fragment table: rows {0,1,2,35,36,37} of Wm1, k-padded to 8
    for (int i = tid; i < 8 * 32; i += blockDim.x) {
        int nt = i >> 5, j = i & 31;
        int q = j >> 3, g = j & 7;
        int col = nt * 8 + g;
        int k0 = 2 * q, k1 = 2 * q + 1;
        const int krow[8] = {0, 1, 2, 35, 36, 37, -1, -1};
        float v0 = (krow[k0] >= 0) ? Wm1[krow[k0] * 64 + col] : 0.f;
        float v1 = (krow[k1] >= 0) ? Wm1[krow[k1] * 64 + col] : 0.f;
        sW1s[i] = packh2(v0, v1);
    }
    for (int i = tid; i < WPB * WARP_BYTES / 4; i += blockDim.x)
        ((uint32_t*)stage)[i] = 0;       // zeros sAs pad cols 6,7 permanently
    if (tid < 64) sB1[tid] = bm1[tid];
    if (tid < 32) sB2[tid] = bm2[tid];
    if (tid < 4)  sB3[tid] = (tid < 3) ? bm3[tid] : 0.f;
    __syncthreads();

    const int wid  = tid >> 5;
    const int lane = tid & 31;
    const int grp  = lane >> 2;
    const int qd   = lane & 3;
    const int fj   = (qd << 3) + grp;
    char* wbase = stage + wid * WARP_BYTES;
    __half* sAs  = (__half*)(wbase + WB_AS);   // [16][8] small-A features
    float*  sYf  = (float*)(wbase + WB_Y);     // [16][68] ysum
    __half* sA2h = (__half*)(wbase + WB_Y);    // reused: h2 staging [16][56]
    __half* sHh  = (__half*)(wbase + WB_H);    // [16][72] h1

    // ---- loop-invariant W2/W3 fragments in registers ----------------------
    uint2 w2r[4][4];
#pragma unroll
    for (int kt = 0; kt < 4; kt++)
#pragma unroll
        for (int nt = 0; nt < 4; nt++) {
            int r0 = kt * 16 + 2 * qd, c = nt * 8 + grp;
            w2r[kt][nt] = make_uint2(
                packh2(Wm2[r0 * 32 + c],       Wm2[(r0 + 1) * 32 + c]),
                packh2(Wm2[(r0 + 8) * 32 + c], Wm2[(r0 + 9) * 32 + c]));
        }
    uint2 w3r[2];
#pragma unroll
    for (int kt = 0; kt < 2; kt++) {
        int r0 = kt * 16 + 2 * qd;
        float v0 = (grp < 3) ? Wm3[r0 * 3 + grp]       : 0.f;
        float v1 = (grp < 3) ? Wm3[(r0 + 1) * 3 + grp] : 0.f;
        float v2 = (grp < 3) ? Wm3[(r0 + 8) * 3 + grp] : 0.f;
        float v3 = (grp < 3) ? Wm3[(r0 + 9) * 3 + grp] : 0.f;
        w3r[kt] = make_uint2(packh2(v0, v1), packh2(v2, v3));
    }
    const float b3c0 = (2 * qd     < 3) ? sB3[2 * qd]     : 0.f;
    const float b3c1 = (2 * qd + 1 < 3) ? sB3[2 * qd + 1] : 0.f;

    const int ntiles = (T + TILE - 1) / TILE;
    const int gw = blockIdx.x * WPB + wid;
    const int gstride = gridDim.x * WPB;

    for (int tile = gw; tile < ntiles; tile += gstride) {
        const int t0 = tile * TILE;

        // ---- gather phase ---------------------------------------------------
        int ia = 0, ib = 0, icx = 0;
        float f12 = 0.f, f13 = 0.f, f23 = 0.f;
        if (lane < TILE) {
            int t = t0 + lane;
            float ea = 0.f, eb = 0.f, ecv = 0.f;
            if (t < T) {
                ia = c12[t]; ib = c13[t]; icx = c23[t];
                f12 = t12[t]; f13 = t13[t]; f23 = t23[t];
                ea = __ldg(ec + ia); eb = __ldg(ec + ib); ecv = __ldg(ec + icx);
            }
            int* sIdx = (int*)sHh;
            sIdx[lane] = ia; sIdx[16 + lane] = ib; sIdx[32 + lane] = icx;
            __half* row = sAs + lane * 8;
            row[0] = __float2half(f12);
            row[1] = __float2half(f13);
            row[2] = __float2half(f23);
            row[3] = __float2half(ea);
            row[4] = __float2half(eb);
            row[5] = __float2half(ecv);
        }
        __syncwarp();
        {
            const int* sIdx = (const int*)sHh;
#pragma unroll
            for (int r = 0; r < TILE; r++) {
                float2 va = *(const float2*)(g_y + (size_t)sIdx[r] * 64 + 2 * lane);
                float2 vb = *(const float2*)(g_y + (size_t)sIdx[16 + r] * 64 + 2 * lane);
                float2 vc = *(const float2*)(g_y + (size_t)sIdx[32 + r] * 64 + 2 * lane);
                *(float2*)(sYf + r * SYS + 2 * lane) =
                    make_float2(va.x + vb.x + vc.x, va.y + vb.y + vc.y);
            }
        }
        __syncwarp();

        // ---- layer 1: ysum + bias into accumulators, 8 m16n8k8 for tri/ec ---
        float a1[8][4];
#pragma unroll
        for (int nt = 0; nt < 8; nt++) {
            float2 bb = *(const float2*)(sB1 + nt * 8 + 2 * qd);
            float2 y0 = *(const float2*)(sYf + grp * SYS + nt * 8 + 2 * qd);
            float2 y1 = *(const float2*)(sYf + (grp + 8) * SYS + nt * 8 + 2 * qd);
            a1[nt][0] = bb.x + y0.x; a1[nt][1] = bb.y + y0.y;
            a1[nt][2] = bb.x + y1.x; a1[nt][3] = bb.y + y1.y;
        }
        {
            uint32_t A0 = *(const uint32_t*)(sAs + grp * 8 + 2 * qd);
            uint32_t A1 = *(const uint32_t*)(sAs + (grp + 8) * 8 + 2 * qd);
#pragma unroll
            for (int nt = 0; nt < 8; nt++) {
                uint32_t b = sW1s[nt * 32 + fj];
                mma_f16_k8(a1[nt][0], a1[nt][1], a1[nt][2], a1[nt][3], A0, A1, b);
            }
        }
        __syncwarp();   // sIdx (in sHh) fully consumed; h1 overwrite OK
#pragma unroll
        for (int nt = 0; nt < 8; nt++) {
            int colc = nt * 8 + 2 * qd;
            *(uint32_t*)(sHh + grp * SHH + colc) =
                packh2(fmaxf(a1[nt][0], 0.f), fmaxf(a1[nt][1], 0.f));
            *(uint32_t*)(sHh + (grp + 8) * SHH + colc) =
                packh2(fmaxf(a1[nt][2], 0.f), fmaxf(a1[nt][3], 0.f));
        }
        __syncwarp();

        // ---- layer 2: [16x64] @ [64x32] fp16 (W2 in registers) --------------
        float a2[4][4];
#pragma unroll
        for (int nt = 0; nt < 4; nt++) {
            float2 bb = *(const float2*)(sB2 + nt * 8 + 2 * qd);
            a2[nt][0] = bb.x; a2[nt][1] = bb.y; a2[nt][2] = bb.x; a2[nt][3] = bb.y;
        }
#pragma unroll
        for (int kt = 0; kt < 4; kt++) {
            uint32_t H0 = *(const uint32_t*)(sHh + grp * SHH + kt * 16 + 2 * qd);
            uint32_t H1 = *(const uint32_t*)(sHh + (grp + 8) * SHH + kt * 16 + 2 * qd);
            uint32_t H2 = *(const uint32_t*)(sHh + grp * SHH + kt * 16 + 2 * qd + 8);
            uint32_t H3 = *(const uint32_t*)(sHh + (grp + 8) * SHH + kt * 16 + 2 * qd + 8);
#pragma unroll
            for (int nt = 0; nt < 4; nt++)
                mma_f16(a2[nt][0], a2[nt][1], a2[nt][2], a2[nt][3],
                        H0, H1, H2, H3, w2r[kt][nt].x, w2r[kt][nt].y);
        }
        __syncwarp();   // sYf reads (layer-1 init) done warp-wide; reuse as h2
#pragma unroll
        for (int nt = 0; nt < 4; nt++) {
            int colc = nt * 8 + 2 * qd;
            *(uint32_t*)(sA2h + grp * SAH + colc) =
                packh2(fmaxf(a2[nt][0], 0.f), fmaxf(a2[nt][1], 0.f));
            *(uint32_t*)(sA2h + (grp + 8) * SAH + colc) =
                packh2(fmaxf(a2[nt][2], 0.f), fmaxf(a2[nt][3], 0.f));
        }
        __syncwarp();

        // ---- layer 3: [16x32] @ [32x8(3)] fp16 (W3 in registers) ------------
        float d0 = b3c0, d1 = b3c1, d2 = b3c0, d3 = b3c1;
#pragma unroll
        for (int kt = 0; kt < 2; kt++) {
            uint32_t A0 = *(const uint32_t*)(sA2h + grp * SAH + kt * 16 + 2 * qd);
            uint32_t A1 = *(const uint32_t*)(sA2h + (grp + 8) * SAH + kt * 16 + 2 * qd);
            uint32_t A2 = *(const uint32_t*)(sA2h + grp * SAH + kt * 16 + 2 * qd + 8);
            uint32_t A3 = *(const uint32_t*)(sA2h + (grp + 8) * SAH + kt * 16 + 2 * qd + 8);
            mma_f16(d0, d1, d2, d3, A0, A1, A2, A3, w3r[kt].x, w3r[kt].y);
        }
        float* sD = (float*)sHh;   // h1 consumed by L2
        if (2 * qd < 3)     { sD[grp * 4 + 2 * qd]     = d0; sD[(grp + 8) * 4 + 2 * qd]     = d2; }
        if (2 * qd + 1 < 3) { sD[grp * 4 + 2 * qd + 1] = d1; sD[(grp + 8) * 4 + 2 * qd + 1] = d3; }
        __syncwarp();

        // ---- epilogue --------------------------------------------------------
        if (lane < TILE && (t0 + lane) < T) {
            float4 dd = *(const float4*)(sD + lane * 4);
            int t = t0 + lane;
            o12[t] = f12 - dd.x;
            o13[t] = f13 - dd.y;
            o23[t] = f23 - dd.z;
            atomicAdd(out_edge + ia,  dd.x);
            atomicAdd(out_edge + ib,  dd.y);
            atomicAdd(out_edge + icx, dd.z);
        }
        __syncwarp();
    }
}

// ---------------- launcher ----------------------------------------------------
extern "C" void kernel_launch(void* const* d_in, const int* in_sizes, int n_in,
                              void* d_out, int out_size) {
    const float* edge_costs = (const float*)d_in[0];
    const float* t12 = (const float*)d_in[1];
    const float* t13 = (const float*)d_in[2];
    const float* t23 = (const float*)d_in[3];
    const int*   c12 = (const int*)d_in[4];
    const int*   c13 = (const int*)d_in[5];
    const int*   c23 = (const int*)d_in[6];
    const int*   eidx = (const int*)d_in[8];
    const float* W1  = (const float*)d_in[10];
    const float* b1  = (const float*)d_in[11];
    const float* W2  = (const float*)d_in[12];
    const float* b2  = (const float*)d_in[13];
    const float* Wm1 = (const float*)d_in[14];
    const float* bm1 = (const float*)d_in[15];
    const float* Wm2 = (const float*)d_in[16];
    const float* bm2 = (const float*)d_in[17];
    const float* Wm3 = (const float*)d_in[18];
    const float* bm3 = (const float*)d_in[19];

    int E = in_sizes[0];       // 200000
    int T = in_sizes[1];       // 2000000
    const int* src = eidx;
    const int* dst = eidx + E;

    float* out_edge = (float*)d_out;
    float* o12 = out_edge + E;
    float* o13 = o12 + T;
    float* o23 = o13 + T;

    const int B = 256;
    k_init <<<(N_NODES * HID + B - 1) / B, B>>>(edge_costs, out_edge, E);
    k_deg  <<<(E + B - 1) / B, B>>>(dst, E);
    k_dinv <<<(N_NODES + B - 1) / B, B>>>();
    k_acc1 <<<(E + B - 1) / B, B>>>(src, dst, E);
    k_node1<<<(N_NODES + B - 1) / B, B>>>(W1, b1, W2);
    k_msg  <<<((size_t)E * 8 + B - 1) / B, B>>>(src, dst, E);
    k_node2<<<(N_NODES * HID + B - 1) / B, B>>>(b2);
    k_y    <<<((size_t)N_NODES * 8 + B - 1) / B, B>>>(Wm1);

    cudaFuncSetAttribute(k_tri, cudaFuncAttributeMaxDynamicSharedMemorySize, SMEM_BYTES);
    k_tri<<<2368, WPB * 32, SMEM_BYTES>>>(t12, t13, t23, c12, c13, c23, edge_costs,
                                          Wm1, bm1, Wm2, bm2, Wm3, bm3,
                                          out_edge, o12, o13, o23, T);
}

// round 17
// speedup vs baseline: 1.3671x; 1.3671x over previous
#include <cuda_runtime.h>
#include <cuda_fp16.h>
#include <cstdint>

#define N_NODES 200000
#define HID 32

// ---------------- scratch (static device globals; no allocation) ----------
__device__ int   g_deg[N_NODES];
__device__ float g_dinv[N_NODES];
__device__ float g_acc1[N_NODES];
__device__ float g_h2 [N_NODES * HID];   // h2 PRE-SCALED by dinv[n]
__device__ float g_acc2[N_NODES * HID];
__device__ float g_x2 [N_NODES * HID];

// ---------------- GCN stages ------------------------------------------------
__global__ void k_init(const float* __restrict__ ec, float* __restrict__ out_edge, int E) {
    int i = blockIdx.x * blockDim.x + threadIdx.x;
    if (i < N_NODES * HID / 4) ((float4*)g_acc2)[i] = make_float4(0.f, 0.f, 0.f, 0.f);
    if (i < N_NODES) { g_deg[i] = 0; g_acc1[i] = 0.f; }
    if (i < E) out_edge[i] = ec[i];
}
__global__ void k_deg(const int* __restrict__ dst, int E) {
    int e = blockIdx.x * blockDim.x + threadIdx.x;
    if (e < E) atomicAdd(&g_deg[dst[e]], 1);
}
__global__ void k_dinv() {
    int n = blockIdx.x * blockDim.x + threadIdx.x;
    if (n < N_NODES) g_dinv[n] = rsqrtf((float)(g_deg[n] + 1));
}
__global__ void k_acc1(const int* __restrict__ src, const int* __restrict__ dst, int E) {
    int e = blockIdx.x * blockDim.x + threadIdx.x;
    if (e < E) atomicAdd(&g_acc1[dst[e]], g_dinv[src[e]]);
}
__global__ void k_node1(const float* __restrict__ W1, const float* __restrict__ b1,
                        const float* __restrict__ W2) {
    __shared__ float sW1[HID], sB1[HID], sW2[HID * HID];
    for (int i = threadIdx.x; i < HID; i += blockDim.x) { sW1[i] = W1[i]; sB1[i] = b1[i]; }
    for (int i = threadIdx.x; i < HID * HID; i += blockDim.x) sW2[i] = W2[i];
    __syncthreads();
    int n = blockIdx.x * blockDim.x + threadIdx.x;
    if (n >= N_NODES) return;
    float dv = g_dinv[n];
    float s1 = dv * (g_acc1[n] + dv);
    float x1[HID];
#pragma unroll
    for (int k = 0; k < HID; k++) x1[k] = fmaxf(fmaf(sW1[k], s1, sB1[k]), 0.f);
    float h2[HID];
#pragma unroll
    for (int j = 0; j < HID; j++) h2[j] = 0.f;
#pragma unroll
    for (int i = 0; i < HID; i++) {
        float xi = x1[i];
#pragma unroll
        for (int j = 0; j < HID; j++) h2[j] = fmaf(xi, sW2[i * HID + j], h2[j]);
    }
    float4* o = (float4*)(g_h2 + (size_t)n * HID);
#pragma unroll
    for (int q = 0; q < 8; q++)
        o[q] = make_float4(h2[4 * q] * dv, h2[4 * q + 1] * dv,
                           h2[4 * q + 2] * dv, h2[4 * q + 3] * dv);
}
__global__ void k_msg(const int* __restrict__ src, const int* __restrict__ dst, int E) {
    int idx = blockIdx.x * blockDim.x + threadIdx.x;
    int e = idx >> 3, k = (idx & 7) << 2;
    if (e >= E) return;
    int s = src[e], d = dst[e];
    float nrm = g_dinv[d];
    float4 v = *(const float4*)(g_h2 + (size_t)s * HID + k);
    float* p = g_acc2 + (size_t)d * HID + k;
    asm volatile("red.global.add.v4.f32 [%0], {%1,%2,%3,%4};"
                 :: "l"(p), "f"(v.x * nrm), "f"(v.y * nrm), "f"(v.z * nrm), "f"(v.w * nrm)
                 : "memory");
}
__global__ void k_node2(const float* __restrict__ b2) {
    int i = blockIdx.x * blockDim.x + threadIdx.x;
    if (i >= N_NODES * HID) return;
    int n = i >> 5, k = i & 31;
    float dv = g_dinv[n];
    g_x2[i] = fmaxf(g_acc2[i] + g_h2[i] * dv + b2[k], 0.f);
}

// ---------------- stage 7: triangle MLP, fp16 MMA, vectorized gather --------
// sA feature layout (halves): [0..2]=t12,t13,t23  [3]=zero
//                             [4..35]=ctx (W1 rows 3..34, 1/3 folded)
//                             [36..38]=ec_a,ec_b,ec_c (W1 rows 35..37)
//                             [39..55]=zero
#define WPB  4
#define TILE 16
#define SAH  56     // sA row stride in halves (112B)
#define SHH  72     // sH row stride in halves (144B)
#define OFF_W1H  0                    // 3*8*32 uint2 = 6144 B
#define OFF_B1B  6144
#define OFF_B2B  6400
#define OFF_B3B  6528
#define OFF_STG  6560
#define WARP_BYTES 4096               // sA 1792 + sH 2304
#define SMEM_BYTES (OFF_STG + WPB * WARP_BYTES)   // 22944

__device__ __forceinline__ uint32_t packh2(float lo, float hi) {
    __half2 h = __floats2half2_rn(lo, hi);
    return *(uint32_t*)&h;
}
__device__ __forceinline__ void mma_f16(
    float& c0, float& c1, float& c2, float& c3,
    uint32_t a0, uint32_t a1, uint32_t a2, uint32_t a3,
    uint32_t b0, uint32_t b1)
{
    asm volatile(
        "mma.sync.aligned.m16n8k16.row.col.f32.f16.f16.f32 "
        "{%0,%1,%2,%3},{%4,%5,%6,%7},{%8,%9},{%0,%1,%2,%3};"
        : "+f"(c0), "+f"(c1), "+f"(c2), "+f"(c3)
        : "r"(a0), "r"(a1), "r"(a2), "r"(a3), "r"(b0), "r"(b1));
}
// sA feature index f -> W1 row (-1 = zero pad); scale 1/3 on ctx block
__device__ __forceinline__ int w1row(int f) {
    if (f < 3) return f;
    if (f >= 4 && f < 39) return f - 1;
    return -1;
}

__global__ void __launch_bounds__(WPB * 32, 5) k_tri(
    const float* __restrict__ t12, const float* __restrict__ t13, const float* __restrict__ t23,
    const int* __restrict__ c12, const int* __restrict__ c13, const int* __restrict__ c23,
    const float* __restrict__ ec,
    const float* __restrict__ Wm1, const float* __restrict__ bm1,
    const float* __restrict__ Wm2, const float* __restrict__ bm2,
    const float* __restrict__ Wm3, const float* __restrict__ bm3,
    float* __restrict__ out_edge,
    float* __restrict__ o12, float* __restrict__ o13, float* __restrict__ o23, int T)
{
    extern __shared__ char smem[];
    uint2* sW1h = (uint2*)(smem + OFF_W1H);   // [(kt*8+nt)*32 + qd*8+grp]
    float* sB1 = (float*)(smem + OFF_B1B);
    float* sB2 = (float*)(smem + OFF_B2B);
    float* sB3 = (float*)(smem + OFF_B3B);
    char*  stage = smem + OFF_STG;

    const int tid = threadIdx.x;

    // ---- W1 fragment table as half2 pairs, re-indexed for new sA layout ---
    for (int i = tid; i < 3 * 8 * 32; i += blockDim.x) {
        int kt = i >> 8, nt = (i >> 5) & 7, j = i & 31;
        int q = j >> 3, g = j & 7;
        int col = nt * 8 + g;
        int f0 = kt * 16 + 2 * q;
        float v[4];
#pragma unroll
        for (int u = 0; u < 4; u++) {
            int f = f0 + (u >> 1) * 8 + (u & 1);
            int r = w1row(f);
            float w = (r >= 0) ? Wm1[r * 64 + col] : 0.f;
            if (f >= 4 && f < 36) w *= (1.f / 3.f);   // ctx block
            v[u] = w;
        }
        sW1h[i] = make_uint2(packh2(v[0], v[1]), packh2(v[2], v[3]));
    }
    // zero all staging (sA cols 3, 39..55 stay zero forever)
    for (int i = tid; i < WPB * WARP_BYTES / 4; i += blockDim.x)
        ((uint32_t*)stage)[i] = 0;
    if (tid < 64) sB1[tid] = bm1[tid];
    if (tid < 32) sB2[tid] = bm2[tid];
    if (tid < 4)  sB3[tid] = (tid < 3) ? bm3[tid] : 0.f;
    __syncthreads();

    const int wid  = tid >> 5;
    const int lane = tid & 31;
    const int grp  = lane >> 2;   // 0..7
    const int qd   = lane & 3;    // 0..3
    const int fj   = (qd << 3) + grp;
    const int sub  = lane >> 3;   // 0..3 (gather row group)
    const int oct  = lane & 7;    // 0..7 (gather float4 column)
    __half* sAh = (__half*)(stage + wid * WARP_BYTES);          // [16][56]
    __half* sHh = (__half*)(stage + wid * WARP_BYTES + 1792);   // [16][72]

    // ---- loop-invariant weight fragments in registers (from global) -------
    uint2 w2r[4][4];
#pragma unroll
    for (int kt = 0; kt < 4; kt++)
#pragma unroll
        for (int nt = 0; nt < 4; nt++) {
            int r0 = kt * 16 + 2 * qd, c = nt * 8 + grp;
            w2r[kt][nt] = make_uint2(
                packh2(Wm2[r0 * 32 + c],       Wm2[(r0 + 1) * 32 + c]),
                packh2(Wm2[(r0 + 8) * 32 + c], Wm2[(r0 + 9) * 32 + c]));
        }
    uint2 w3r[2];
#pragma unroll
    for (int kt = 0; kt < 2; kt++) {
        int r0 = kt * 16 + 2 * qd;
        float v0 = (grp < 3) ? Wm3[r0 * 3 + grp]       : 0.f;
        float v1 = (grp < 3) ? Wm3[(r0 + 1) * 3 + grp] : 0.f;
        float v2 = (grp < 3) ? Wm3[(r0 + 8) * 3 + grp] : 0.f;
        float v3 = (grp < 3) ? Wm3[(r0 + 9) * 3 + grp] : 0.f;
        w3r[kt] = make_uint2(packh2(v0, v1), packh2(v2, v3));
    }
    const float b3c0 = (2 * qd     < 3) ? sB3[2 * qd]     : 0.f;
    const float b3c1 = (2 * qd + 1 < 3) ? sB3[2 * qd + 1] : 0.f;

    const int ntiles = (T + TILE - 1) / TILE;
    const int gw = blockIdx.x * WPB + wid;
    const int gstride = gridDim.x * WPB;

    for (int tile = gw; tile < ntiles; tile += gstride) {
        const int t0 = tile * TILE;

        // ---- gather phase (smem index broadcast + float4 row loads) --------
        int ia = 0, ib = 0, icx = 0;
        float f12 = 0.f, f13 = 0.f, f23 = 0.f;
        if (lane < TILE) {
            int t = t0 + lane;
            float ea = 0.f, eb = 0.f, ecv = 0.f;
            if (t < T) {
                ia = c12[t]; ib = c13[t]; icx = c23[t];
                f12 = t12[t]; f13 = t13[t]; f23 = t23[t];
                ea = __ldg(ec + ia); eb = __ldg(ec + ib); ecv = __ldg(ec + icx);
            }
            int* sIdx = (int*)sHh;
            sIdx[lane] = ia; sIdx[16 + lane] = ib; sIdx[32 + lane] = icx;
            __half* row = sAh + lane * SAH;
            row[0]  = __float2half(f12);
            row[1]  = __float2half(f13);
            row[2]  = __float2half(f23);
            row[36] = __float2half(ea);
            row[37] = __float2half(eb);
            row[38] = __float2half(ecv);
        }
        __syncwarp();
        {
            const int* sIdx = (const int*)sHh;
#pragma unroll
            for (int q = 0; q < 4; q++) {
                int r = q * 4 + sub;
                int ja = sIdx[r], jb = sIdx[16 + r], jc = sIdx[32 + r];
                float4 va = __ldg((const float4*)(g_x2 + (size_t)ja * HID + 4 * oct));
                float4 vb = __ldg((const float4*)(g_x2 + (size_t)jb * HID + 4 * oct));
                float4 vc = __ldg((const float4*)(g_x2 + (size_t)jc * HID + 4 * oct));
                float sx = va.x + vb.x + vc.x;
                float sy = va.y + vb.y + vc.y;
                float sz = va.z + vb.z + vc.z;
                float sw = va.w + vb.w + vc.w;
                *(uint2*)(sAh + r * SAH + 4 + 4 * oct) =
                    make_uint2(packh2(sx, sy), packh2(sz, sw));   // 1/3 in sW1
            }
        }
        __syncwarp();

        // ---- layer 1: [16x48] @ [48x64] fp16 -------------------------------
        float a1[8][4];
#pragma unroll
        for (int nt = 0; nt < 8; nt++) {
            float2 bb = *(const float2*)(sB1 + nt * 8 + 2 * qd);
            a1[nt][0] = bb.x; a1[nt][1] = bb.y; a1[nt][2] = bb.x; a1[nt][3] = bb.y;
        }
#pragma unroll
        for (int kt = 0; kt < 3; kt++) {
            uint32_t A0 = *(const uint32_t*)(sAh + grp * SAH + kt * 16 + 2 * qd);
            uint32_t A1 = *(const uint32_t*)(sAh + (grp + 8) * SAH + kt * 16 + 2 * qd);
            uint32_t A2 = *(const uint32_t*)(sAh + grp * SAH + kt * 16 + 2 * qd + 8);
            uint32_t A3 = *(const uint32_t*)(sAh + (grp + 8) * SAH + kt * 16 + 2 * qd + 8);
#pragma unroll
            for (int nt = 0; nt < 8; nt++) {
                uint2 b = sW1h[(kt * 8 + nt) * 32 + fj];
                mma_f16(a1[nt][0], a1[nt][1], a1[nt][2], a1[nt][3], A0, A1, A2, A3, b.x, b.y);
            }
        }
        __syncwarp();   // sIdx region (sHh) reused for h1 below
#pragma unroll
        for (int nt = 0; nt < 8; nt++) {
            int colc = nt * 8 + 2 * qd;
            *(uint32_t*)(sHh + grp * SHH + colc) =
                packh2(fmaxf(a1[nt][0], 0.f), fmaxf(a1[nt][1], 0.f));
            *(uint32_t*)(sHh + (grp + 8) * SHH + colc) =
                packh2(fmaxf(a1[nt][2], 0.f), fmaxf(a1[nt][3], 0.f));
        }
        __syncwarp();

        // ---- layer 2: [16x64] @ [64x32] fp16 (W2 in registers) -------------
        float a2[4][4];
#pragma unroll
        for (int nt = 0; nt < 4; nt++) {
            float2 bb = *(const float2*)(sB2 + nt * 8 + 2 * qd);
            a2[nt][0] = bb.x; a2[nt][1] = bb.y; a2[nt][2] = bb.x; a2[nt][3] = bb.y;
        }
#pragma unroll
        for (int kt = 0; kt < 4; kt++) {
            uint32_t H0 = *(const uint32_t*)(sHh + grp * SHH + kt * 16 + 2 * qd);
            uint32_t H1 = *(const uint32_t*)(sHh + (grp + 8) * SHH + kt * 16 + 2 * qd);
            uint32_t H2 = *(const uint32_t*)(sHh + grp * SHH + kt * 16 + 2 * qd + 8);
            uint32_t H3 = *(const uint32_t*)(sHh + (grp + 8) * SHH + kt * 16 + 2 * qd + 8);
#pragma unroll
            for (int nt = 0; nt < 4; nt++)
                mma_f16(a2[nt][0], a2[nt][1], a2[nt][2], a2[nt][3],
                        H0, H1, H2, H3, w2r[kt][nt].x, w2r[kt][nt].y);
        }
#pragma unroll
        for (int nt = 0; nt < 4; nt++) {
            int colc = nt * 8 + 2 * qd;
            *(uint32_t*)(sAh + grp * SAH + colc) =
                packh2(fmaxf(a2[nt][0], 0.f), fmaxf(a2[nt][1], 0.f));
            *(uint32_t*)(sAh + (grp + 8) * SAH + colc) =
                packh2(fmaxf(a2[nt][2], 0.f), fmaxf(a2[nt][3], 0.f));
        }
        __syncwarp();

        // ---- layer 3: [16x32] @ [32x8(3)] fp16 (W3 in registers) -----------
        float d0 = b3c0, d1 = b3c1, d2 = b3c0, d3 = b3c1;
#pragma unroll
        for (int kt = 0; kt < 2; kt++) {
            uint32_t A0 = *(const uint32_t*)(sAh + grp * SAH + kt * 16 + 2 * qd);
            uint32_t A1 = *(const uint32_t*)(sAh + (grp + 8) * SAH + kt * 16 + 2 * qd);
            uint32_t A2 = *(const uint32_t*)(sAh + grp * SAH + kt * 16 + 2 * qd + 8);
            uint32_t A3 = *(const uint32_t*)(sAh + (grp + 8) * SAH + kt * 16 + 2 * qd + 8);
            mma_f16(d0, d1, d2, d3, A0, A1, A2, A3, w3r[kt].x, w3r[kt].y);
        }
        float* sD = (float*)sHh;   // reuse as [16][4] f32
        if (2 * qd < 3)     { sD[grp * 4 + 2 * qd]     = d0; sD[(grp + 8) * 4 + 2 * qd]     = d2; }
        if (2 * qd + 1 < 3) { sD[grp * 4 + 2 * qd + 1] = d1; sD[(grp + 8) * 4 + 2 * qd + 1] = d3; }
        __syncwarp();

        // ---- epilogue -------------------------------------------------------
        if (lane < TILE && (t0 + lane) < T) {
            float4 dd = *(const float4*)(sD + lane * 4);
            int t = t0 + lane;
            o12[t] = f12 - dd.x;
            o13[t] = f13 - dd.y;
            o23[t] = f23 - dd.z;
            atomicAdd(out_edge + ia,  dd.x);
            atomicAdd(out_edge + ib,  dd.y);
            atomicAdd(out_edge + icx, dd.z);
        }
        __syncwarp();

        // restore zero at sA cols 39 (clobbered? no — writes stop at col 38)
        // cols 3 and 39..55 were never written; still zero. nothing to do.
    }
}

// ---------------- launcher ----------------------------------------------------
extern "C" void kernel_launch(void* const* d_in, const int* in_sizes, int n_in,
                              void* d_out, int out_size) {
    const float* edge_costs = (const float*)d_in[0];
    const float* t12 = (const float*)d_in[1];
    const float* t13 = (const float*)d_in[2];
    const float* t23 = (const float*)d_in[3];
    const int*   c12 = (const int*)d_in[4];
    const int*   c13 = (const int*)d_in[5];
    const int*   c23 = (const int*)d_in[6];
    const int*   eidx = (const int*)d_in[8];
    const float* W1  = (const float*)d_in[10];
    const float* b1  = (const float*)d_in[11];
    const float* W2  = (const float*)d_in[12];
    const float* b2  = (const float*)d_in[13];
    const float* Wm1 = (const float*)d_in[14];
    const float* bm1 = (const float*)d_in[15];
    const float* Wm2 = (const float*)d_in[16];
    const float* bm2 = (const float*)d_in[17];
    const float* Wm3 = (const float*)d_in[18];
    const float* bm3 = (const float*)d_in[19];

    int E = in_sizes[0];       // 200000
    int T = in_sizes[1];       // 2000000
    const int* src = eidx;
    const int* dst = eidx + E;

    float* out_edge = (float*)d_out;
    float* o12 = out_edge + E;
    float* o13 = o12 + T;
    float* o23 = o13 + T;

    const int B = 256;
    k_init <<<(N_NODES * HID + B - 1) / B, B>>>(edge_costs, out_edge, E);
    k_deg  <<<(E + B - 1) / B, B>>>(dst, E);
    k_dinv <<<(N_NODES + B - 1) / B, B>>>();
    k_acc1 <<<(E + B - 1) / B, B>>>(src, dst, E);
    k_node1<<<(N_NODES + B - 1) / B, B>>>(W1, b1, W2);
    k_msg  <<<((size_t)E * 8 + B - 1) / B, B>>>(src, dst, E);
    k_node2<<<(N_NODES * HID + B - 1) / B, B>>>(b2);

    cudaFuncSetAttribute(k_tri, cudaFuncAttributeMaxDynamicSharedMemorySize, SMEM_BYTES);
    k_tri<<<2368, WPB * 32, SMEM_BYTES>>>(t12, t13, t23, c12, c13, c23, edge_costs,
                                          Wm1, bm1, Wm2, bm2, Wm3, bm3,
                                          out_edge, o12, o13, o23, T);
}